// round 3
// baseline (speedup 1.0000x reference)
#include <cuda_runtime.h>
#include <math.h>

#define EPSV 1e-6f
#define B_ 8
#define N_ 4096
#define P_ 16
#define H_ 128
#define NC_ 64                 // points per chunk
#define NCHUNKS_ (N_/NC_)      // 64
#define HIDDEN_ 128
#define RDIM_ 64
#define PH_ (P_*H_)            // 2048

// scratch: partial [b][chunk][stat(3)][p][h]  and per-(b,chunk,p) assign sums
__device__ __align__(16) float g_part[B_ * NCHUNKS_ * 3 * PH_];   // 12.6 MB
__device__ float g_massp[B_ * NCHUNKS_ * P_];

__device__ __forceinline__ float neg_inf() { return __int_as_float(0xff800000u); }

// ---------------------------------------------------------------------------
// Phase 1: per-(b, n-chunk) weighted sum / sumsq / masked-max partials
// ---------------------------------------------------------------------------
__global__ __launch_bounds__(128) void phase1_kernel(
    const float* __restrict__ pf, const float* __restrict__ am)
{
    const int c = blockIdx.x;      // chunk 0..63
    const int b = blockIdx.y;      // batch 0..7
    const int t = threadIdx.x;     // h lane 0..127

    __shared__ __align__(16) float a_sm[NC_][P_];
    __shared__ __align__(16) float q_sm[NC_][P_];   // bias: 0 if active, -inf if not

    // load assign chunk (1024 floats) + build bias
    {
        const float4* ap = (const float4*)(am + (size_t)(b * N_ + c * NC_) * P_);
        #pragma unroll
        for (int i = 0; i < 2; i++) {
            int idx = i * 128 + t;               // 256 float4 total
            float4 v = ap[idx];
            ((float4*)a_sm)[idx] = v;
            float4 qq;
            qq.x = (v.x <= EPSV) ? neg_inf() : 0.f;
            qq.y = (v.y <= EPSV) ? neg_inf() : 0.f;
            qq.z = (v.z <= EPSV) ? neg_inf() : 0.f;
            qq.w = (v.w <= EPSV) ? neg_inf() : 0.f;
            ((float4*)q_sm)[idx] = qq;
        }
    }
    __syncthreads();

    float s1[P_], s2[P_], mx[P_];
    #pragma unroll
    for (int p = 0; p < P_; p++) { s1[p] = 0.f; s2[p] = 0.f; mx[p] = neg_inf(); }

    const float* pfp = pf + (size_t)(b * N_ + c * NC_) * H_ + t;

    #pragma unroll 4
    for (int n = 0; n < NC_; n++) {
        float v  = pfp[n * H_];
        float vv = v * v;
        float4 a0 = *(const float4*)&a_sm[n][0];
        float4 a1 = *(const float4*)&a_sm[n][4];
        float4 a2 = *(const float4*)&a_sm[n][8];
        float4 a3 = *(const float4*)&a_sm[n][12];
        float4 q0 = *(const float4*)&q_sm[n][0];
        float4 q1 = *(const float4*)&q_sm[n][4];
        float4 q2 = *(const float4*)&q_sm[n][8];
        float4 q3 = *(const float4*)&q_sm[n][12];
#define CORE(idx, A, Q) { \
        s1[idx] = fmaf((A), v,  s1[idx]); \
        s2[idx] = fmaf((A), vv, s2[idx]); \
        mx[idx] = fmaxf(mx[idx], fmaf((A), v, (Q))); }
        CORE(0,  a0.x, q0.x) CORE(1,  a0.y, q0.y) CORE(2,  a0.z, q0.z) CORE(3,  a0.w, q0.w)
        CORE(4,  a1.x, q1.x) CORE(5,  a1.y, q1.y) CORE(6,  a1.z, q1.z) CORE(7,  a1.w, q1.w)
        CORE(8,  a2.x, q2.x) CORE(9,  a2.y, q2.y) CORE(10, a2.z, q2.z) CORE(11, a2.w, q2.w)
        CORE(12, a3.x, q3.x) CORE(13, a3.y, q3.y) CORE(14, a3.z, q3.z) CORE(15, a3.w, q3.w)
#undef CORE
    }

    // write partials: layout [b][c][stat][p][h], h contiguous
    float* base = g_part + (size_t)((b * NCHUNKS_ + c) * 3) * PH_ + t;
    #pragma unroll
    for (int p = 0; p < P_; p++) {
        base[0 * PH_ + p * H_] = s1[p];
        base[1 * PH_ + p * H_] = s2[p];
        base[2 * PH_ + p * H_] = mx[p];
    }

    // per-p assign sum for this chunk (a_sm unchanged since sync; safe to read)
    if (t < P_) {
        float s = 0.f;
        #pragma unroll 8
        for (int n = 0; n < NC_; n++) s += a_sm[n][t];
        g_massp[(b * NCHUNKS_ + c) * P_ + t] = s;
    }
}

// ---------------------------------------------------------------------------
// Phase 2: reduce partials, finalize stats, fused 2-layer MLP (4 rows/block)
// ---------------------------------------------------------------------------
__global__ __launch_bounds__(128) void phase2_kernel(
    const float* __restrict__ sq, const float* __restrict__ W1,
    const float* __restrict__ b1, const float* __restrict__ W2,
    const float* __restrict__ b2, float* __restrict__ out)
{
    const int t = threadIdx.x;
    const int r = t >> 5;           // row-within-block 0..3
    const int q = t & 31;           // h-quad index 0..31
    const int row = blockIdx.x * 4 + r;   // 0..127
    const int b = row >> 4;
    const int p = row & 15;

    __shared__ __align__(16) float ri[4 * H_][4];   // residual input, [k][row]
    __shared__ __align__(16) float hd[HIDDEN_][4];  // hidden activations

    float4 S1 = make_float4(0.f, 0.f, 0.f, 0.f);
    float4 S2 = make_float4(0.f, 0.f, 0.f, 0.f);
    float4 M  = make_float4(neg_inf(), neg_inf(), neg_inf(), neg_inf());
    float sumA = 0.f;

    const float* mp = g_massp + (size_t)b * NCHUNKS_ * P_ + p;
    const float* pb = g_part + (size_t)(b * NCHUNKS_ * 3) * PH_ + p * H_ + q * 4;

    #pragma unroll 4
    for (int c = 0; c < NCHUNKS_; c++) {
        const float* bb = pb + (size_t)c * 3 * PH_;
        float4 x = *(const float4*)(bb);
        float4 y = *(const float4*)(bb + PH_);
        float4 z = *(const float4*)(bb + 2 * PH_);
        S1.x += x.x; S1.y += x.y; S1.z += x.z; S1.w += x.w;
        S2.x += y.x; S2.y += y.y; S2.z += y.z; S2.w += y.w;
        M.x = fmaxf(M.x, z.x); M.y = fmaxf(M.y, z.y);
        M.z = fmaxf(M.z, z.z); M.w = fmaxf(M.w, z.w);
        sumA += mp[c * P_];
    }

    float mass = fmaxf(sumA, EPSV);
    float inv  = 1.f / mass;

    float po[4], va[4], mf[4];
    {
        float s1a[4] = {S1.x, S1.y, S1.z, S1.w};
        float s2a[4] = {S2.x, S2.y, S2.z, S2.w};
        float ma[4]  = {M.x,  M.y,  M.z,  M.w};
        #pragma unroll
        for (int i = 0; i < 4; i++) {
            float mu = s1a[i] * inv;
            po[i] = mu;
            va[i] = (s2a[i] - 2.f * mu * s1a[i] + mu * mu * sumA) * inv;
            mf[i] = isfinite(ma[i]) ? ma[i] : 0.f;
        }
    }

    const int h0 = q * 4;
    float4 sqv = *(const float4*)(sq + (size_t)(b * P_ + p) * H_ + h0);
    {
        float sqa[4] = {sqv.x, sqv.y, sqv.z, sqv.w};
        #pragma unroll
        for (int i = 0; i < 4; i++) {
            ri[h0 + i][r]          = sqa[i];
            ri[H_ + h0 + i][r]     = po[i];
            ri[2 * H_ + h0 + i][r] = mf[i];
            ri[3 * H_ + h0 + i][r] = va[i];
        }
    }
    __syncthreads();

    // GEMM1: hd[j][row] = relu(b1[j] + sum_k ri[k][row] * W1[k][j])
    {
        const int j = t;
        float bv = b1[j];
        float a0 = bv, a1 = bv, a2 = bv, a3 = bv;
        #pragma unroll 8
        for (int k = 0; k < 4 * H_; k++) {
            float4 rv = *(const float4*)&ri[k][0];   // broadcast
            float w = W1[k * HIDDEN_ + j];           // coalesced
            a0 = fmaf(rv.x, w, a0);
            a1 = fmaf(rv.y, w, a1);
            a2 = fmaf(rv.z, w, a2);
            a3 = fmaf(rv.w, w, a3);
        }
        float4 hv = make_float4(fmaxf(a0, 0.f), fmaxf(a1, 0.f),
                                fmaxf(a2, 0.f), fmaxf(a3, 0.f));
        *(float4*)&hd[j][0] = hv;
    }
    __syncthreads();

    // GEMM2: out[row][j] = b2[j] + sum_k hd[k][row] * W2[k][j]
    if (t < RDIM_) {
        const int j = t;
        float bv = b2[j];
        float a0 = bv, a1 = bv, a2 = bv, a3 = bv;
        #pragma unroll 8
        for (int k = 0; k < HIDDEN_; k++) {
            float4 hv = *(const float4*)&hd[k][0];   // broadcast
            float w = W2[k * RDIM_ + j];             // coalesced
            a0 = fmaf(hv.x, w, a0);
            a1 = fmaf(hv.y, w, a1);
            a2 = fmaf(hv.z, w, a2);
            a3 = fmaf(hv.w, w, a3);
        }
        const int r0 = blockIdx.x * 4;
        out[(r0 + 0) * RDIM_ + j] = a0;
        out[(r0 + 1) * RDIM_ + j] = a1;
        out[(r0 + 2) * RDIM_ + j] = a2;
        out[(r0 + 3) * RDIM_ + j] = a3;
    }
}

// ---------------------------------------------------------------------------
extern "C" void kernel_launch(void* const* d_in, const int* in_sizes, int n_in,
                              void* d_out, int out_size)
{
    const float* sq = (const float*)d_in[0];
    const float* pf = (const float*)d_in[1];
    const float* am = (const float*)d_in[2];
    const float* W1 = (const float*)d_in[3];
    const float* b1 = (const float*)d_in[4];
    const float* W2 = (const float*)d_in[5];
    const float* b2 = (const float*)d_in[6];
    float* out = (float*)d_out;

    dim3 g1(NCHUNKS_, B_);
    phase1_kernel<<<g1, 128>>>(pf, am);
    phase2_kernel<<<32, 128>>>(sq, W1, b1, W2, b2, out);
}

// round 5
// speedup vs baseline: 1.9007x; 1.9007x over previous
#include <cuda_runtime.h>
#include <math.h>

#define EPSV 1e-6f
#define B_ 8
#define N_ 4096
#define P_ 16
#define H_ 128
#define NC_ 64                 // points per chunk
#define NCHUNKS_ (N_/NC_)      // 64
#define HIDDEN_ 128
#define RDIM_ 64
#define PH_ (P_*H_)            // 2048

// scratch: partial [b][chunk][stat(3)][p][h]  and per-(b,chunk,p) assign sums
__device__ __align__(16) float g_part[B_ * NCHUNKS_ * 3 * PH_];   // 12.6 MB
__device__ float g_massp[B_ * NCHUNKS_ * P_];

__device__ __forceinline__ float neg_inf() { return __int_as_float(0xff800000u); }

// ---------------------------------------------------------------------------
// Phase 1: per-(b, n-chunk) weighted sum / sumsq / masked-max partials
// ---------------------------------------------------------------------------
__global__ __launch_bounds__(128) void phase1_kernel(
    const float* __restrict__ pf, const float* __restrict__ am)
{
    const int c = blockIdx.x;      // chunk 0..63
    const int b = blockIdx.y;      // batch 0..7
    const int t = threadIdx.x;     // h lane 0..127

    __shared__ __align__(16) float a_sm[NC_][P_];
    __shared__ __align__(16) float q_sm[NC_][P_];   // bias: 0 if active, -inf if not

    // load assign chunk (1024 floats) + build bias
    {
        const float4* ap = (const float4*)(am + (size_t)(b * N_ + c * NC_) * P_);
        #pragma unroll
        for (int i = 0; i < 2; i++) {
            int idx = i * 128 + t;               // 256 float4 total
            float4 v = ap[idx];
            ((float4*)a_sm)[idx] = v;
            float4 qq;
            qq.x = (v.x <= EPSV) ? neg_inf() : 0.f;
            qq.y = (v.y <= EPSV) ? neg_inf() : 0.f;
            qq.z = (v.z <= EPSV) ? neg_inf() : 0.f;
            qq.w = (v.w <= EPSV) ? neg_inf() : 0.f;
            ((float4*)q_sm)[idx] = qq;
        }
    }
    __syncthreads();

    float s1[P_], s2[P_], mx[P_];
    #pragma unroll
    for (int p = 0; p < P_; p++) { s1[p] = 0.f; s2[p] = 0.f; mx[p] = neg_inf(); }

    const float* pfp = pf + (size_t)(b * N_ + c * NC_) * H_ + t;

    #pragma unroll 4
    for (int n = 0; n < NC_; n++) {
        float v  = pfp[n * H_];
        float vv = v * v;
        float4 a0 = *(const float4*)&a_sm[n][0];
        float4 a1 = *(const float4*)&a_sm[n][4];
        float4 a2 = *(const float4*)&a_sm[n][8];
        float4 a3 = *(const float4*)&a_sm[n][12];
        float4 q0 = *(const float4*)&q_sm[n][0];
        float4 q1 = *(const float4*)&q_sm[n][4];
        float4 q2 = *(const float4*)&q_sm[n][8];
        float4 q3 = *(const float4*)&q_sm[n][12];
#define CORE(idx, A, Q) { \
        s1[idx] = fmaf((A), v,  s1[idx]); \
        s2[idx] = fmaf((A), vv, s2[idx]); \
        mx[idx] = fmaxf(mx[idx], fmaf((A), v, (Q))); }
        CORE(0,  a0.x, q0.x) CORE(1,  a0.y, q0.y) CORE(2,  a0.z, q0.z) CORE(3,  a0.w, q0.w)
        CORE(4,  a1.x, q1.x) CORE(5,  a1.y, q1.y) CORE(6,  a1.z, q1.z) CORE(7,  a1.w, q1.w)
        CORE(8,  a2.x, q2.x) CORE(9,  a2.y, q2.y) CORE(10, a2.z, q2.z) CORE(11, a2.w, q2.w)
        CORE(12, a3.x, q3.x) CORE(13, a3.y, q3.y) CORE(14, a3.z, q3.z) CORE(15, a3.w, q3.w)
#undef CORE
    }

    // write partials: layout [b][c][stat][p][h], h contiguous
    float* base = g_part + (size_t)((b * NCHUNKS_ + c) * 3) * PH_ + t;
    #pragma unroll
    for (int p = 0; p < P_; p++) {
        base[0 * PH_ + p * H_] = s1[p];
        base[1 * PH_ + p * H_] = s2[p];
        base[2 * PH_ + p * H_] = mx[p];
    }

    // per-p assign sum for this chunk (a_sm unchanged since sync; safe to read)
    if (t < P_) {
        float s = 0.f;
        #pragma unroll 8
        for (int n = 0; n < NC_; n++) s += a_sm[n][t];
        g_massp[(b * NCHUNKS_ + c) * P_ + t] = s;
    }
}

// ---------------------------------------------------------------------------
// Phase 2: one block per output row (128 blocks x 128 threads).
// Warp-parallel partial reduction + warp-split fused 2-layer MLP.
// ---------------------------------------------------------------------------
__global__ __launch_bounds__(128) void phase2_kernel(
    const float* __restrict__ sq, const float* __restrict__ W1,
    const float* __restrict__ b1, const float* __restrict__ W2,
    const float* __restrict__ b2, float* __restrict__ out)
{
    const int t   = threadIdx.x;
    const int row = blockIdx.x;        // 0..127
    const int b   = row >> 4;
    const int p   = row & 15;

    __shared__ __align__(16) float ri[4 * H_];          // residual input (512)
    __shared__ __align__(16) float sS1[4][H_];
    __shared__ __align__(16) float sS2[4][H_];
    __shared__ __align__(16) float sM [4][H_];
    __shared__ float massred[NCHUNKS_];
    __shared__ __align__(16) float p1[4][HIDDEN_];      // GEMM1 warp partials
    __shared__ __align__(16) float hd[HIDDEN_];
    __shared__ __align__(16) float p2[8][RDIM_];        // GEMM2 group partials

    // ---------- Stage 1: reduce chunk partials (4 warps x 16 chunks) ----------
    {
        const int q = t & 31;          // h-quad index
        const int g = t >> 5;          // chunk group 0..3
        float4 S1 = make_float4(0.f, 0.f, 0.f, 0.f);
        float4 S2 = make_float4(0.f, 0.f, 0.f, 0.f);
        float4 M  = make_float4(neg_inf(), neg_inf(), neg_inf(), neg_inf());

        const float* pb = g_part + (size_t)((b * NCHUNKS_ + g) * 3) * PH_
                        + p * H_ + q * 4;
        #pragma unroll
        for (int cc = 0; cc < 16; cc++) {
            const float* bb = pb + (size_t)cc * 4 * 3 * PH_;   // chunk = g + 4*cc
            float4 x = *(const float4*)(bb);
            float4 y = *(const float4*)(bb + PH_);
            float4 z = *(const float4*)(bb + 2 * PH_);
            S1.x += x.x; S1.y += x.y; S1.z += x.z; S1.w += x.w;
            S2.x += y.x; S2.y += y.y; S2.z += y.z; S2.w += y.w;
            M.x = fmaxf(M.x, z.x); M.y = fmaxf(M.y, z.y);
            M.z = fmaxf(M.z, z.z); M.w = fmaxf(M.w, z.w);
        }
        *(float4*)&sS1[g][q * 4] = S1;
        *(float4*)&sS2[g][q * 4] = S2;
        *(float4*)&sM [g][q * 4] = M;

        if (t < NCHUNKS_)
            massred[t] = g_massp[(b * NCHUNKS_ + t) * P_ + p];
    }
    __syncthreads();

    // ---------- Stage 2: finalize stats, build residual row ----------
    {
        float sumA = 0.f;
        #pragma unroll
        for (int i = 0; i < NCHUNKS_; i++) sumA += massred[i];   // smem broadcast
        float mass = fmaxf(sumA, EPSV);
        float inv  = 1.f / mass;

        float s1 = sS1[0][t] + sS1[1][t] + sS1[2][t] + sS1[3][t];
        float s2 = sS2[0][t] + sS2[1][t] + sS2[2][t] + sS2[3][t];
        float mx = fmaxf(fmaxf(sM[0][t], sM[1][t]), fmaxf(sM[2][t], sM[3][t]));

        float mu = s1 * inv;
        ri[t]          = sq[(size_t)(b * P_ + p) * H_ + t];
        ri[H_ + t]     = mu;
        ri[2 * H_ + t] = isfinite(mx) ? mx : 0.f;
        ri[3 * H_ + t] = (s2 - 2.f * mu * s1 + mu * mu * sumA) * inv;
    }
    __syncthreads();

    // ---------- GEMM1: 512 x 128, warp-split over K ----------
    {
        const int jq = t & 31;         // output j-quad: j = 4*jq..4*jq+3
        const int kg = t >> 5;         // K group 0..3 (128 k each)
        const float* Wp = W1 + (size_t)(kg * H_) * HIDDEN_ + jq * 4;
        const float* rp = ri + kg * H_;
        float4 accA = make_float4(0.f, 0.f, 0.f, 0.f);
        float4 accB = make_float4(0.f, 0.f, 0.f, 0.f);
        #pragma unroll 8
        for (int k = 0; k < H_; k += 2) {
            float4 w0 = *(const float4*)(Wp + (size_t)k * HIDDEN_);
            float  r0 = rp[k];
            accA.x = fmaf(r0, w0.x, accA.x);
            accA.y = fmaf(r0, w0.y, accA.y);
            accA.z = fmaf(r0, w0.z, accA.z);
            accA.w = fmaf(r0, w0.w, accA.w);
            float4 w1 = *(const float4*)(Wp + (size_t)(k + 1) * HIDDEN_);
            float  r1 = rp[k + 1];
            accB.x = fmaf(r1, w1.x, accB.x);
            accB.y = fmaf(r1, w1.y, accB.y);
            accB.z = fmaf(r1, w1.z, accB.z);
            accB.w = fmaf(r1, w1.w, accB.w);
        }
        float4 acc = make_float4(accA.x + accB.x, accA.y + accB.y,
                                 accA.z + accB.z, accA.w + accB.w);
        *(float4*)&p1[kg][jq * 4] = acc;
    }
    __syncthreads();

    // combine warp partials + bias + relu
    hd[t] = fmaxf(b1[t] + p1[0][t] + p1[1][t] + p1[2][t] + p1[3][t], 0.f);
    __syncthreads();

    // ---------- GEMM2: 128 x 64, 8-way split over K ----------
    {
        const int jq = t & 15;         // j = 4*jq..4*jq+3
        const int kg = t >> 4;         // K group 0..7 (16 k each)
        const float* Wp = W2 + (size_t)(kg * 16) * RDIM_ + jq * 4;
        const float* hp = hd + kg * 16;
        float4 accA = make_float4(0.f, 0.f, 0.f, 0.f);
        float4 accB = make_float4(0.f, 0.f, 0.f, 0.f);
        #pragma unroll
        for (int k = 0; k < 16; k += 2) {
            float4 w0 = *(const float4*)(Wp + (size_t)k * RDIM_);
            float  r0 = hp[k];
            accA.x = fmaf(r0, w0.x, accA.x);
            accA.y = fmaf(r0, w0.y, accA.y);
            accA.z = fmaf(r0, w0.z, accA.z);
            accA.w = fmaf(r0, w0.w, accA.w);
            float4 w1 = *(const float4*)(Wp + (size_t)(k + 1) * RDIM_);
            float  r1 = hp[k + 1];
            accB.x = fmaf(r1, w1.x, accB.x);
            accB.y = fmaf(r1, w1.y, accB.y);
            accB.z = fmaf(r1, w1.z, accB.z);
            accB.w = fmaf(r1, w1.w, accB.w);
        }
        float4 acc = make_float4(accA.x + accB.x, accA.y + accB.y,
                                 accA.z + accB.z, accA.w + accB.w);
        *(float4*)&p2[kg][jq * 4] = acc;
    }
    __syncthreads();

    if (t < RDIM_) {
        float o = b2[t];
        #pragma unroll
        for (int g = 0; g < 8; g++) o += p2[g][t];
        out[(size_t)row * RDIM_ + t] = o;
    }
}

// ---------------------------------------------------------------------------
extern "C" void kernel_launch(void* const* d_in, const int* in_sizes, int n_in,
                              void* d_out, int out_size)
{
    const float* sq = (const float*)d_in[0];
    const float* pf = (const float*)d_in[1];
    const float* am = (const float*)d_in[2];
    const float* W1 = (const float*)d_in[3];
    const float* b1 = (const float*)d_in[4];
    const float* W2 = (const float*)d_in[5];
    const float* b2 = (const float*)d_in[6];
    float* out = (float*)d_out;

    dim3 g1(NCHUNKS_, B_);
    phase1_kernel<<<g1, 128>>>(pf, am);
    phase2_kernel<<<128, 128>>>(sq, W1, b1, W2, b2, out);
}